// round 16
// baseline (speedup 1.0000x reference)
#include <cuda_runtime.h>
#include <cuda_fp16.h>
#include <cstdint>

#define NB 2
#define NS 2048
#define ND 768
#define NH 12
#define NHD 64
#define NFF 3072
#define NM (NB*NS)   // 4096 rows

// ---------------- scratch (static device allocations, allowed) ----------------
__device__ __half g_xh[NM*ND];
__device__ __half g_wqh[ND*ND];
__device__ __half g_wkh[ND*ND];
__device__ __half g_wvh[ND*ND];
__device__ __half g_woh[ND*ND];
__device__ __half g_w1h[(size_t)NFF*ND];
__device__ __half g_w2h[(size_t)ND*NFF];
__device__ __half g_qh[NB*NH*NS*NHD];
__device__ __half g_kh[NB*NH*NS*NHD];
__device__ __half g_vh[NB*NH*NS*NHD];   // TRANSPOSED: [b,h,hd,s]
__device__ __half g_attnh[NM*ND];
__device__ __half g_x1h[NM*ND];
__device__ __half g_ffh[(size_t)NM*NFF];
__device__ float g_tmp[NM*ND];
__device__ float g_x1[NM*ND];

// ---------------- common tensor-core helpers ----------------
__device__ __forceinline__ void ldsm4(uint32_t& r0, uint32_t& r1,
                                      uint32_t& r2, uint32_t& r3, uint32_t addr) {
    asm volatile("ldmatrix.sync.aligned.m8n8.x4.shared.b16 {%0,%1,%2,%3}, [%4];"
                 : "=r"(r0), "=r"(r1), "=r"(r2), "=r"(r3) : "r"(addr));
}

__device__ __forceinline__ void mma_f16(float* c, const uint32_t* a, const uint32_t* b) {
    asm volatile(
        "mma.sync.aligned.m16n8k16.row.col.f32.f16.f16.f32 "
        "{%0,%1,%2,%3}, {%4,%5,%6,%7}, {%8,%9}, {%0,%1,%2,%3};"
        : "+f"(c[0]), "+f"(c[1]), "+f"(c[2]), "+f"(c[3])
        : "r"(a[0]), "r"(a[1]), "r"(a[2]), "r"(a[3]), "r"(b[0]), "r"(b[1]));
}

__device__ __forceinline__ void cp16(uint32_t daddr, const void* gaddr) {
    asm volatile("cp.async.cg.shared.global [%0], [%1], 16;" :: "r"(daddr), "l"(gaddr));
}

__device__ __forceinline__ float ex2f(float x) {
    float r;
    asm("ex2.approx.f32 %0, %1;" : "=f"(r) : "f"(x));
    return r;
}

// ---------------------------------------------------------------------------
// Fused fp32 -> fp16 conversion over ALL 7 tensors in ONE launch.
// ---------------------------------------------------------------------------
#define CVT4(S, D, I) do { \
    float4 v = *reinterpret_cast<const float4*>((S) + (I)); \
    *reinterpret_cast<__half2*>((D) + (I))     = __floats2half2_rn(v.x, v.y); \
    *reinterpret_cast<__half2*>((D) + (I) + 2) = __floats2half2_rn(v.z, v.w); \
} while (0)

#define N_X  (NM*ND)
#define N_W  (ND*ND)
#define N_WF (NFF*ND)
#define CVT_TOTAL (N_X + 4*N_W + 2*N_WF)   // 10,223,616

__global__ __launch_bounds__(256) void cvt7(
    const float* __restrict__ sx, __half* __restrict__ dx,
    const float* __restrict__ s1, __half* __restrict__ d1,
    const float* __restrict__ s2, __half* __restrict__ d2,
    const float* __restrict__ s3, __half* __restrict__ d3,
    const float* __restrict__ s4, __half* __restrict__ d4,
    const float* __restrict__ s5, __half* __restrict__ d5,
    const float* __restrict__ s6, __half* __restrict__ d6)
{
    int i = (blockIdx.x * 256 + threadIdx.x) << 2;
    if (i < N_X) { CVT4(sx, dx, i); return; }
    i -= N_X;
    if (i < N_W) { CVT4(s1, d1, i); return; }
    i -= N_W;
    if (i < N_W) { CVT4(s2, d2, i); return; }
    i -= N_W;
    if (i < N_W) { CVT4(s3, d3, i); return; }
    i -= N_W;
    if (i < N_W) { CVT4(s4, d4, i); return; }
    i -= N_W;
    if (i < N_WF) { CVT4(s5, d5, i); return; }
    i -= N_WF;
    if (i < N_WF) { CVT4(s6, d6, i); return; }
}

// ===========================================================================
// FP16 tensor-core GEMM (R14 winner, unchanged): 128x64 CTA tile, 4 warps,
// BK=32, 3-stage cp.async pipeline, occupancy 4 (reg-capped 128).
// ===========================================================================
#define BK 32
#define HSTR 40                        // halfs per smem row (80 B, bank-safe)
#define ABUF_H (128*HSTR)              // 5120 halfs
#define BBUF_H (64*HSTR)               // 2560 halfs
#define GSTAGES 3
#define GEMM_SMEM ((GSTAGES*ABUF_H + GSTAGES*BBUF_H) * 2)   // 46080 bytes

__global__ __launch_bounds__(128, 4) void gemm_h(
    const __half* __restrict__ A,
    const __half* __restrict__ w0, const __half* __restrict__ w1,
    const __half* __restrict__ w2,
    const float* __restrict__ bi0, const float* __restrict__ bi1,
    const float* __restrict__ bi2,
    const float* __restrict__ res,
    __half* __restrict__ h0, __half* __restrict__ h1, __half* __restrict__ h2,
    float* __restrict__ f0,
    int M, int Nper, int K, int relu, int out16,
    int mode0, int mode1, int mode2)
{
    extern __shared__ __half smh[];
    const int tid = threadIdx.x, lane = tid & 31, warp = tid >> 5;
    const int wm = (warp & 1) << 6;      // 0 / 64
    const int wn = (warp >> 1) << 5;     // 0 / 32
    const int m0 = blockIdx.y << 7;

    const int nglob = blockIdx.x << 6;
    const int wsel = nglob / Nper;
    const int n0 = nglob - wsel * Nper;
    const __half* W   = (wsel == 0) ? w0  : (wsel == 1) ? w1  : w2;
    const float* bias = (wsel == 0) ? bi0 : (wsel == 1) ? bi1 : bi2;
    __half* H         = (wsel == 0) ? h0  : (wsel == 1) ? h1  : h2;
    const int mode    = (wsel == 0) ? mode0 : (wsel == 1) ? mode1 : mode2;

    const uint32_t s_base = (uint32_t)__cvta_generic_to_shared(smh);

    const int a_row = wm + (lane & 15);
    uint32_t a_off[4];
    #pragma unroll
    for (int mi = 0; mi < 4; mi++)
        a_off[mi] = (uint32_t)((a_row + mi * 16) * HSTR * 2 + ((lane >> 4) << 4));
    const int b_row = wn + (lane & 7) + ((lane >> 4) << 3);
    uint32_t b_off[2];
    #pragma unroll
    for (int j = 0; j < 2; j++)
        b_off[j] = (uint32_t)((b_row + j * 16) * HSTR * 2 + (((lane >> 3) & 1) << 4));

    float acc[4][4][4] = {};
    const int nt = K / BK;

    auto issue = [&](int t, int st) {
        const int k0 = t * BK;
        #pragma unroll
        for (int c = 0; c < 4; c++) {
            const int idx = tid + (c << 7);        // 0..511
            const int row = idx >> 2;              // 0..127
            const int hc = (idx & 3) << 3;         // half col 0,8,16,24
            const uint32_t da = s_base + (uint32_t)((st * ABUF_H + row * HSTR + hc) << 1);
            cp16(da, A + (size_t)(m0 + row) * K + k0 + hc);
        }
        #pragma unroll
        for (int c = 0; c < 2; c++) {
            const int idx = tid + (c << 7);        // 0..255
            const int row = idx >> 2;              // 0..63
            const int hc = (idx & 3) << 3;
            const uint32_t dw = s_base +
                (uint32_t)(((GSTAGES * ABUF_H + st * BBUF_H) + row * HSTR + hc) << 1);
            cp16(dw, W + (size_t)(n0 + row) * K + k0 + hc);
        }
        asm volatile("cp.async.commit_group;");
    };

    issue(0, 0);
    if (nt > 1) issue(1, 1);

    int buf = 0;
    for (int t = 0; t < nt; t++) {
        if (t + 1 < nt)
            asm volatile("cp.async.wait_group 1;");
        else
            asm volatile("cp.async.wait_group 0;");
        __syncthreads();

        if (t + 2 < nt) {
            int nb = buf + 2; if (nb >= GSTAGES) nb -= GSTAGES;
            issue(t + 2, nb);
        }

        const uint32_t abase = s_base + (uint32_t)((buf * ABUF_H) << 1);
        const uint32_t bbase = s_base + (uint32_t)(((GSTAGES * ABUF_H + buf * BBUF_H)) << 1);

        #pragma unroll
        for (int kk = 0; kk < 2; kk++) {           // 2 x k16 per BK=32
            uint32_t af[4][4], bf[4][2];
            #pragma unroll
            for (int mi = 0; mi < 4; mi++)
                ldsm4(af[mi][0], af[mi][1], af[mi][2], af[mi][3],
                      abase + a_off[mi] + kk * 32);
            #pragma unroll
            for (int j = 0; j < 2; j++)
                ldsm4(bf[2*j][0], bf[2*j][1], bf[2*j+1][0], bf[2*j+1][1],
                      bbase + b_off[j] + kk * 32);
            #pragma unroll
            for (int mi = 0; mi < 4; mi++)
                #pragma unroll
                for (int nj = 0; nj < 4; nj++)
                    mma_f16(acc[mi][nj], af[mi], bf[nj]);
        }
        buf = (buf + 1 == GSTAGES) ? 0 : buf + 1;
    }

    // ------------------------------ epilogue -------------------------------
    #pragma unroll
    for (int mi = 0; mi < 4; mi++) {
        const int m = m0 + wm + mi * 16 + (lane >> 2);
        #pragma unroll
        for (int nj = 0; nj < 4; nj++) {
            const int n = n0 + wn + nj * 8 + ((lane & 3) << 1);
            const float b0v = bias[n], b1v = bias[n + 1];
            #pragma unroll
            for (int r = 0; r < 2; r++) {
                const int mm = m + r * 8;
                float v0 = acc[mi][nj][r * 2 + 0] + b0v;
                float v1 = acc[mi][nj][r * 2 + 1] + b1v;
                if (relu) { v0 = fmaxf(v0, 0.0f); v1 = fmaxf(v1, 0.0f); }
                if (res) {
                    v0 += res[(size_t)mm * Nper + n];
                    v1 += res[(size_t)mm * Nper + n + 1];
                }
                if (out16) {
                    if (mode == 1) {
                        int h = n >> 6, hd = n & 63;
                        int b = mm >> 11, s = mm & (NS - 1);
                        *reinterpret_cast<__half2*>(
                            &H[(((size_t)(b * NH + h)) * NS + s) * NHD + hd]) =
                            __floats2half2_rn(v0, v1);
                    } else if (mode == 2) {
                        int h = n >> 6, hd = n & 63;
                        int b = mm >> 11, s = mm & (NS - 1);
                        const size_t vb = (((size_t)(b * NH + h)) * NHD + hd) * NS + s;
                        H[vb] = __float2half_rn(v0);
                        H[vb + NS] = __float2half_rn(v1);
                    } else {
                        *reinterpret_cast<__half2*>(&H[(size_t)mm * Nper + n]) =
                            __floats2half2_rn(v0, v1);
                    }
                } else {
                    *reinterpret_cast<float2*>(&f0[(size_t)mm * Nper + n]) =
                        make_float2(v0, v1);
                }
            }
        }
    }
}

// ===========================================================================
// FP16 tensor-core flash attention. 128 q-rows per CTA, 256 threads / 8 warps
// (per-warp tile unchanged: 16 q x 64 k). K/V fill traffic halves per unit
// work; occupancy 2 CTAs = 16 warps/SM. Diagonal-first tiles; warps whose
// rows are fully masked in a tile skip its compute entirely.
// ===========================================================================
#define ASTR 72                         // halfs per attn smem row (144 B)
#define ATILE_H (64*ASTR)               // 4608 halfs = 9216 B
#define QTILE_H (128*ASTR)              // Qs/Ps: 128 rows
#define ATT_SMEM ((QTILE_H + 4*ATILE_H)*2)   // 55296 bytes
#define LOG2E 1.4426950408889634f

__global__ __launch_bounds__(256, 2) void attn_tc(
    const __half* __restrict__ Q, const __half* __restrict__ K,
    const __half* __restrict__ V, __half* __restrict__ O)
{
    extern __shared__ __half smh[];

    const int tid = threadIdx.x, lane = tid & 31, warp = tid >> 5;
    const int q0 = (int)(gridDim.x - 1 - blockIdx.x) << 7;   // heavy CTAs first
    const int bh = blockIdx.y;
    const int h = bh % NH, b = bh / NH;
    const size_t base = (size_t)bh * NS * NHD;
    const float slope2 = exp2f(-(8.0f / NH) * (float)(h + 1)) * LOG2E;
    const float qk_scale = 0.125f * LOG2E;

    const uint32_t s_base = (uint32_t)__cvta_generic_to_shared(smh);
    const uint32_t qs_b = s_base;                                   // Qs / Ps (128 rows)
    const uint32_t kb[2] = { s_base + QTILE_H * 2,
                             s_base + (QTILE_H + 2 * ATILE_H) * 2 };
    const uint32_t vb[2] = { s_base + (QTILE_H + 1 * ATILE_H) * 2,
                             s_base + (QTILE_H + 3 * ATILE_H) * 2 };
    __half* Ps = smh;

    const int a_row = (warp << 4) + (lane & 15);      // warp 0..7 -> rows 0..127
    const uint32_t a_off = (uint32_t)(a_row * ASTR * 2 + ((lane >> 4) << 4));
    const int b_row = (lane & 7) + ((lane >> 4) << 3);
    const uint32_t b_colb = (uint32_t)(((lane >> 3) & 1) << 4);
    uint32_t b_off[4];
    #pragma unroll
    for (int jj = 0; jj < 4; jj++)
        b_off[jj] = (uint32_t)((b_row + 16 * jj) * ASTR * 2) + b_colb;

    // fill one 64-key tile (K rows [s][d] + Vt rows [d][s]); 2 chunks/thread each
    auto fill = [&](int buf, int kn) {
        #pragma unroll
        for (int c = 0; c < 2; c++) {
            const int idx = tid + (c << 8);        // 0..511
            const int row = idx >> 3;              // 0..63
            const int hc = (idx & 7) << 3;         // half col 0..56
            const uint32_t soff = (uint32_t)((row * ASTR + hc) << 1);
            cp16(kb[buf] + soff, K + base + (size_t)(kn + row) * NHD + hc);
            cp16(vb[buf] + soff, V + base + (size_t)row * NS + kn + hc);
        }
        asm volatile("cp.async.commit_group;");
    };

    const int nt = (q0 >> 6) + 2;                   // 64-key tiles covering q0+127
    const int tf = nt - 1;                          // top (diagonal) tile first
    const int qmax_w = q0 + (warp << 4) + 15;       // last q row this warp owns

    // Q tile (128 rows) via cp.async, committed with tile tf's fill
    #pragma unroll
    for (int c = 0; c < 4; c++) {
        const int idx = tid + (c << 8);            // 0..1023
        const int row = idx >> 3;                  // 0..127
        const int hc = (idx & 7) << 3;
        cp16(qs_b + (uint32_t)((row * ASTR + hc) << 1),
             Q + base + (size_t)(q0 + row) * NHD + hc);
    }
    fill(0, tf << 6);
    asm volatile("cp.async.wait_group 0;");
    __syncthreads();

    uint32_t qf[4][4];
    #pragma unroll
    for (int kk = 0; kk < 4; kk++)
        ldsm4(qf[kk][0], qf[kk][1], qf[kk][2], qf[kk][3], qs_b + a_off + kk * 32);

    float acc_o[8][4] = {};
    float m_r[2] = {-1e30f, -1e30f};
    float l_r[2] = {0.0f, 0.0f};
    const int qrow = q0 + (warp << 4) + (lane >> 2);

    for (int i = 0; i < nt; i++) {
        const int t = tf - i;
        const int k0 = t << 6;
        const int buf = i & 1;
        if (i > 0) {
            asm volatile("cp.async.wait_group 0;");
            __syncthreads();
        }

        if (i + 1 < nt)
            fill(buf ^ 1, (t - 1) << 6);

        if (k0 <= qmax_w) {   // tile not fully masked for this warp
            // ---- S = Q K^T  (4 x k16 over d=64) ----
            float sc[8][4] = {};
            #pragma unroll
            for (int kk = 0; kk < 4; kk++) {
                uint32_t bf[8][2];
                #pragma unroll
                for (int jj = 0; jj < 4; jj++)
                    ldsm4(bf[2*jj][0], bf[2*jj][1], bf[2*jj+1][0], bf[2*jj+1][1],
                          kb[buf] + b_off[jj] + kk * 32);
                #pragma unroll
                for (int j = 0; j < 8; j++)
                    mma_f16(sc[j], qf[kk], bf[j]);
            }

            // ---- scale + alibi + causal + online softmax (log2 domain) ----
            #pragma unroll
            for (int r = 0; r < 2; r++) {
                const int q = qrow + r * 8;
                float mx = -1e30f;
                #pragma unroll
                for (int j = 0; j < 8; j++) {
                    int kc = k0 + 8 * j + ((lane & 3) << 1);
                    float s0 = fmaf(sc[j][2*r+0], qk_scale, slope2 * (float)(kc - q));
                    float s1 = fmaf(sc[j][2*r+1], qk_scale, slope2 * (float)(kc + 1 - q));
                    if (kc > q)     s0 = -1e30f;
                    if (kc + 1 > q) s1 = -1e30f;
                    sc[j][2*r+0] = s0; sc[j][2*r+1] = s1;
                    mx = fmaxf(mx, fmaxf(s0, s1));
                }
                mx = fmaxf(mx, __shfl_xor_sync(0xffffffffu, mx, 1));
                mx = fmaxf(mx, __shfl_xor_sync(0xffffffffu, mx, 2));
                const float mnew = fmaxf(m_r[r], mx);
                if (__any_sync(0xffffffffu, mnew > m_r[r])) {
                    const float alpha = ex2f(m_r[r] - mnew);
                    l_r[r] *= alpha;
                    #pragma unroll
                    for (int j = 0; j < 8; j++) {
                        acc_o[j][2*r+0] *= alpha;
                        acc_o[j][2*r+1] *= alpha;
                    }
                    m_r[r] = mnew;
                }
                float sum = 0.0f;
                #pragma unroll
                for (int j = 0; j < 8; j++) {
                    float p0 = ex2f(sc[j][2*r+0] - m_r[r]);
                    float p1 = ex2f(sc[j][2*r+1] - m_r[r]);
                    sc[j][2*r+0] = p0; sc[j][2*r+1] = p1;
                    sum += p0 + p1;
                }
                sum += __shfl_xor_sync(0xffffffffu, sum, 1);
                sum += __shfl_xor_sync(0xffffffffu, sum, 2);
                l_r[r] += sum;
            }

            // ---- stage P as fp16 in smem (warp-private rows of Ps) ----
            __syncwarp();
            #pragma unroll
            for (int r = 0; r < 2; r++) {
                const int rl = (warp << 4) + (lane >> 2) + r * 8;
                #pragma unroll
                for (int j = 0; j < 8; j++) {
                    *reinterpret_cast<__half2*>(&Ps[rl * ASTR + 8 * j + ((lane & 3) << 1)]) =
                        __floats2half2_rn(sc[j][2*r+0], sc[j][2*r+1]);
                }
            }
            __syncwarp();

            // ---- O += P V  (4 x k16 over keys) ----
            #pragma unroll
            for (int kk = 0; kk < 4; kk++) {
                uint32_t pf[4];
                ldsm4(pf[0], pf[1], pf[2], pf[3], qs_b + a_off + kk * 32);
                uint32_t bf[8][2];
                #pragma unroll
                for (int jj = 0; jj < 4; jj++)
                    ldsm4(bf[2*jj][0], bf[2*jj][1], bf[2*jj+1][0], bf[2*jj+1][1],
                          vb[buf] + b_off[jj] + kk * 32);
                #pragma unroll
                for (int j = 0; j < 8; j++)
                    mma_f16(acc_o[j], pf, bf[j]);
            }
        }
    }

    // ---- normalize and write O (fp16, (B,S,D)) ----
    #pragma unroll
    for (int r = 0; r < 2; r++) {
        const int q = qrow + r * 8;
        const float inv = 1.0f / l_r[r];
        #pragma unroll
        for (int j = 0; j < 8; j++) {
            const int d = (h << 6) + 8 * j + ((lane & 3) << 1);
            *reinterpret_cast<__half2*>(&O[((size_t)(b * NS + q)) * ND + d]) =
                __floats2half2_rn(acc_o[j][2*r+0] * inv, acc_o[j][2*r+1] * inv);
        }
    }
}

// ---------------------------------------------------------------------------
// LayerNorm over last dim (768). Single pass, float4, shuffle reductions.
// Optional dual output: fp32 (Y) and fp16 (Y16) for the next GEMM operand.
// ---------------------------------------------------------------------------
__global__ __launch_bounds__(256) void ln_kernel(
    const float* __restrict__ X, const float* __restrict__ g,
    const float* __restrict__ be, float* __restrict__ Y,
    __half* __restrict__ Y16)
{
    __shared__ float sred[18];
    const int row = blockIdx.x;
    const int tid = threadIdx.x, lane = tid & 31, warp = tid >> 5;

    float4 xv = make_float4(0.0f, 0.0f, 0.0f, 0.0f);
    if (tid < 192)
        xv = *reinterpret_cast<const float4*>(X + (size_t)row * ND + (tid << 2));

    float s = xv.x + xv.y + xv.z + xv.w;
    float q = fmaf(xv.x, xv.x, fmaf(xv.y, xv.y, fmaf(xv.z, xv.z, xv.w * xv.w)));
    #pragma unroll
    for (int off = 16; off > 0; off >>= 1) {
        s += __shfl_xor_sync(0xffffffffu, s, off);
        q += __shfl_xor_sync(0xffffffffu, q, off);
    }
    if (lane == 0) { sred[warp] = s; sred[warp + 8] = q; }
    __syncthreads();
    if (warp == 0) {
        float s2 = (lane < 8) ? sred[lane] : 0.0f;
        float q2 = (lane < 8) ? sred[lane + 8] : 0.0f;
        #pragma unroll
        for (int off = 4; off > 0; off >>= 1) {
            s2 += __shfl_xor_sync(0xffffffffu, s2, off);
            q2 += __shfl_xor_sync(0xffffffffu, q2, off);
        }
        if (lane == 0) {
            float mu = s2 * (1.0f / ND);
            float var = q2 * (1.0f / ND) - mu * mu;
            sred[16] = mu;
            sred[17] = rsqrtf(var + 1e-5f);
        }
    }
    __syncthreads();
    const float mu = sred[16], rstd = sred[17];

    if (tid < 192) {
        float4 gv = *reinterpret_cast<const float4*>(g + (tid << 2));
        float4 bv = *reinterpret_cast<const float4*>(be + (tid << 2));
        float4 yv;
        yv.x = (xv.x - mu) * rstd * gv.x + bv.x;
        yv.y = (xv.y - mu) * rstd * gv.y + bv.y;
        yv.z = (xv.z - mu) * rstd * gv.z + bv.z;
        yv.w = (xv.w - mu) * rstd * gv.w + bv.w;
        *reinterpret_cast<float4*>(Y + (size_t)row * ND + (tid << 2)) = yv;
        if (Y16) {
            *reinterpret_cast<__half2*>(Y16 + (size_t)row * ND + (tid << 2)) =
                __floats2half2_rn(yv.x, yv.y);
            *reinterpret_cast<__half2*>(Y16 + (size_t)row * ND + (tid << 2) + 2) =
                __floats2half2_rn(yv.z, yv.w);
        }
    }
}

// ---------------------------------------------------------------------------
extern "C" void kernel_launch(void* const* d_in, const int* in_sizes, int n_in,
                              void* d_out, int out_size)
{
    const float* x   = (const float*)d_in[0];
    // d_in[1] = mask, d_in[2] = alibi_bias  (computed analytically, not read)
    const float* wq  = (const float*)d_in[3];
    const float* bq  = (const float*)d_in[4];
    const float* wk  = (const float*)d_in[5];
    const float* bk  = (const float*)d_in[6];
    const float* wv  = (const float*)d_in[7];
    const float* bv  = (const float*)d_in[8];
    const float* wo  = (const float*)d_in[9];
    const float* bo  = (const float*)d_in[10];
    const float* w1  = (const float*)d_in[11];
    const float* b1  = (const float*)d_in[12];
    const float* w2  = (const float*)d_in[13];
    const float* b2  = (const float*)d_in[14];
    const float* g1  = (const float*)d_in[15];
    const float* be1 = (const float*)d_in[16];
    const float* g2  = (const float*)d_in[17];
    const float* be2 = (const float*)d_in[18];
    float* out = (float*)d_out;

    __half *xh, *wqh, *wkh, *wvh, *woh, *w1h, *w2h;
    __half *qh, *kh, *vh, *attnh, *x1h, *ffh;
    float *tmp_p, *x1_p;
    cudaGetSymbolAddress((void**)&xh,   g_xh);
    cudaGetSymbolAddress((void**)&wqh,  g_wqh);
    cudaGetSymbolAddress((void**)&wkh,  g_wkh);
    cudaGetSymbolAddress((void**)&wvh,  g_wvh);
    cudaGetSymbolAddress((void**)&woh,  g_woh);
    cudaGetSymbolAddress((void**)&w1h,  g_w1h);
    cudaGetSymbolAddress((void**)&w2h,  g_w2h);
    cudaGetSymbolAddress((void**)&qh,   g_qh);
    cudaGetSymbolAddress((void**)&kh,   g_kh);
    cudaGetSymbolAddress((void**)&vh,   g_vh);
    cudaGetSymbolAddress((void**)&attnh,g_attnh);
    cudaGetSymbolAddress((void**)&x1h,  g_x1h);
    cudaGetSymbolAddress((void**)&ffh,  g_ffh);
    cudaGetSymbolAddress((void**)&tmp_p,g_tmp);
    cudaGetSymbolAddress((void**)&x1_p, g_x1);

    cudaFuncSetAttribute(attn_tc, cudaFuncAttributeMaxDynamicSharedMemorySize, ATT_SMEM);
    cudaFuncSetAttribute(gemm_h, cudaFuncAttributeMaxDynamicSharedMemorySize, GEMM_SMEM);
    // lift the default smem carveout so 4 gemm CTAs (184 KB) fit per SM
    cudaFuncSetAttribute(gemm_h, cudaFuncAttributePreferredSharedMemoryCarveout, 100);
    cudaFuncSetAttribute(attn_tc, cudaFuncAttributePreferredSharedMemoryCarveout, 100);

    // ONE fused fp32->fp16 conversion launch (x + all 6 weights)
    cvt7<<<CVT_TOTAL/1024, 256>>>(x, xh, wq, wqh, wk, wkh, wv, wvh,
                                  wo, woh, w1, w1h, w2, w2h);

    // Fused QKV (one launch, 1152 CTAs): Q,K -> (B,H,S,HD) fp16; V -> (B,H,HD,S) fp16
    gemm_h<<<dim3(3*ND/64, NM/128), 128, GEMM_SMEM>>>(
        xh, wqh, wkh, wvh, bq, bk, bv, nullptr,
        qh, kh, vh, nullptr,
        NM, ND, ND, 0, 1, 1, 1, 2);

    // attention -> fp16 (B,S,D); 128 q rows per CTA
    attn_tc<<<dim3(NS/128, NB*NH), 256, ATT_SMEM>>>(qh, kh, vh, attnh);

    // O projection + residual (fp32 out), then LN1 (dual out)
    gemm_h<<<dim3(ND/64, NM/128), 128, GEMM_SMEM>>>(
        attnh, woh, woh, woh, bo, bo, bo, x,
        nullptr, nullptr, nullptr, tmp_p,
        NM, ND, ND, 0, 0, 0, 0, 0);
    ln_kernel<<<NM, 256>>>(tmp_p, g1, be1, x1_p, x1h);

    // FFN1 (relu, fp16 out)
    gemm_h<<<dim3(NFF/64, NM/128), 128, GEMM_SMEM>>>(
        x1h, w1h, w1h, w1h, b1, b1, b1, nullptr,
        ffh, ffh, ffh, nullptr,
        NM, NFF, ND, 1, 1, 0, 0, 0);
    // FFN2 + residual (fp32 out)
    gemm_h<<<dim3(ND/64, NM/128), 128, GEMM_SMEM>>>(
        ffh, w2h, w2h, w2h, b2, b2, b2, x1_p,
        nullptr, nullptr, nullptr, tmp_p,
        NM, ND, NFF, 0, 0, 0, 0, 0);
    ln_kernel<<<NM, 256>>>(tmp_p, g2, be2, out, nullptr);
}

// round 17
// speedup vs baseline: 1.0185x; 1.0185x over previous
#include <cuda_runtime.h>
#include <cuda_fp16.h>
#include <cstdint>

#define NB 2
#define NS 2048
#define ND 768
#define NH 12
#define NHD 64
#define NFF 3072
#define NM (NB*NS)   // 4096 rows

// ---------------- scratch (static device allocations, allowed) ----------------
__device__ __half g_xh[NM*ND];
__device__ __half g_wqh[ND*ND];
__device__ __half g_wkh[ND*ND];
__device__ __half g_wvh[ND*ND];
__device__ __half g_woh[ND*ND];
__device__ __half g_w1h[(size_t)NFF*ND];
__device__ __half g_w2h[(size_t)ND*NFF];
__device__ __half g_qh[NB*NH*NS*NHD];
__device__ __half g_kh[NB*NH*NS*NHD];
__device__ __half g_vh[NB*NH*NS*NHD];   // TRANSPOSED: [b,h,hd,s]
__device__ __half g_attnh[NM*ND];
__device__ __half g_x1h[NM*ND];
__device__ __half g_ffh[(size_t)NM*NFF];
__device__ float g_part[2*(size_t)NM*ND];   // split-K partials
__device__ float g_x1[NM*ND];

// ---------------- common tensor-core helpers ----------------
__device__ __forceinline__ void ldsm4(uint32_t& r0, uint32_t& r1,
                                      uint32_t& r2, uint32_t& r3, uint32_t addr) {
    asm volatile("ldmatrix.sync.aligned.m8n8.x4.shared.b16 {%0,%1,%2,%3}, [%4];"
                 : "=r"(r0), "=r"(r1), "=r"(r2), "=r"(r3) : "r"(addr));
}

__device__ __forceinline__ void mma_f16(float* c, const uint32_t* a, const uint32_t* b) {
    asm volatile(
        "mma.sync.aligned.m16n8k16.row.col.f32.f16.f16.f32 "
        "{%0,%1,%2,%3}, {%4,%5,%6,%7}, {%8,%9}, {%0,%1,%2,%3};"
        : "+f"(c[0]), "+f"(c[1]), "+f"(c[2]), "+f"(c[3])
        : "r"(a[0]), "r"(a[1]), "r"(a[2]), "r"(a[3]), "r"(b[0]), "r"(b[1]));
}

__device__ __forceinline__ void cp16(uint32_t daddr, const void* gaddr) {
    asm volatile("cp.async.cg.shared.global [%0], [%1], 16;" :: "r"(daddr), "l"(gaddr));
}

__device__ __forceinline__ float ex2f(float x) {
    float r;
    asm("ex2.approx.f32 %0, %1;" : "=f"(r) : "f"(x));
    return r;
}

// ---------------------------------------------------------------------------
// Fused fp32 -> fp16 conversion over ALL 7 tensors in ONE launch.
// ---------------------------------------------------------------------------
#define CVT4(S, D, I) do { \
    float4 v = *reinterpret_cast<const float4*>((S) + (I)); \
    *reinterpret_cast<__half2*>((D) + (I))     = __floats2half2_rn(v.x, v.y); \
    *reinterpret_cast<__half2*>((D) + (I) + 2) = __floats2half2_rn(v.z, v.w); \
} while (0)

#define N_X  (NM*ND)
#define N_W  (ND*ND)
#define N_WF (NFF*ND)
#define CVT_TOTAL (N_X + 4*N_W + 2*N_WF)   // 10,223,616

__global__ __launch_bounds__(256) void cvt7(
    const float* __restrict__ sx, __half* __restrict__ dx,
    const float* __restrict__ s1, __half* __restrict__ d1,
    const float* __restrict__ s2, __half* __restrict__ d2,
    const float* __restrict__ s3, __half* __restrict__ d3,
    const float* __restrict__ s4, __half* __restrict__ d4,
    const float* __restrict__ s5, __half* __restrict__ d5,
    const float* __restrict__ s6, __half* __restrict__ d6)
{
    int i = (blockIdx.x * 256 + threadIdx.x) << 2;
    if (i < N_X) { CVT4(sx, dx, i); return; }
    i -= N_X;
    if (i < N_W) { CVT4(s1, d1, i); return; }
    i -= N_W;
    if (i < N_W) { CVT4(s2, d2, i); return; }
    i -= N_W;
    if (i < N_W) { CVT4(s3, d3, i); return; }
    i -= N_W;
    if (i < N_W) { CVT4(s4, d4, i); return; }
    i -= N_W;
    if (i < N_WF) { CVT4(s5, d5, i); return; }
    i -= N_WF;
    if (i < N_WF) { CVT4(s6, d6, i); return; }
}

// ===========================================================================
// FP16 tensor-core GEMM: 128x64 CTA tile, 4 warps, BK=32, 3-stage cp.async.
// ksplit: blockIdx.z in {0,1} computes half the K range and writes RAW fp32
// partials to f0 + z*M*Nper (no bias/relu/res) -> doubles CTAs for small-N
// GEMMs (O-proj, FFN2) whose grids were residency-limited.
// ===========================================================================
#define BK 32
#define HSTR 40                        // halfs per smem row (80 B, bank-safe)
#define ABUF_H (128*HSTR)              // 5120 halfs
#define BBUF_H (64*HSTR)               // 2560 halfs
#define GSTAGES 3
#define GEMM_SMEM ((GSTAGES*ABUF_H + GSTAGES*BBUF_H) * 2)   // 46080 bytes

__global__ __launch_bounds__(128, 4) void gemm_h(
    const __half* __restrict__ A,
    const __half* __restrict__ w0, const __half* __restrict__ w1,
    const __half* __restrict__ w2,
    const float* __restrict__ bi0, const float* __restrict__ bi1,
    const float* __restrict__ bi2,
    const float* __restrict__ res,
    __half* __restrict__ h0, __half* __restrict__ h1, __half* __restrict__ h2,
    float* __restrict__ f0,
    int M, int Nper, int K, int relu, int out16,
    int mode0, int mode1, int mode2, int ksplit)
{
    extern __shared__ __half smh[];
    const int tid = threadIdx.x, lane = tid & 31, warp = tid >> 5;
    const int wm = (warp & 1) << 6;      // 0 / 64
    const int wn = (warp >> 1) << 5;     // 0 / 32
    const int m0 = blockIdx.y << 7;

    const int nglob = blockIdx.x << 6;
    const int wsel = nglob / Nper;
    const int n0 = nglob - wsel * Nper;
    const __half* W   = (wsel == 0) ? w0  : (wsel == 1) ? w1  : w2;
    const float* bias = (wsel == 0) ? bi0 : (wsel == 1) ? bi1 : bi2;
    __half* H         = (wsel == 0) ? h0  : (wsel == 1) ? h1  : h2;
    const int mode    = (wsel == 0) ? mode0 : (wsel == 1) ? mode1 : mode2;

    // split-K range
    const int Keff = ksplit ? (K >> 1) : K;
    const int kbase = ksplit ? (int)blockIdx.z * Keff : 0;

    const uint32_t s_base = (uint32_t)__cvta_generic_to_shared(smh);

    const int a_row = wm + (lane & 15);
    uint32_t a_off[4];
    #pragma unroll
    for (int mi = 0; mi < 4; mi++)
        a_off[mi] = (uint32_t)((a_row + mi * 16) * HSTR * 2 + ((lane >> 4) << 4));
    const int b_row = wn + (lane & 7) + ((lane >> 4) << 3);
    uint32_t b_off[2];
    #pragma unroll
    for (int j = 0; j < 2; j++)
        b_off[j] = (uint32_t)((b_row + j * 16) * HSTR * 2 + (((lane >> 3) & 1) << 4));

    float acc[4][4][4] = {};
    const int nt = Keff / BK;

    auto issue = [&](int t, int st) {
        const int k0 = kbase + t * BK;
        #pragma unroll
        for (int c = 0; c < 4; c++) {
            const int idx = tid + (c << 7);        // 0..511
            const int row = idx >> 2;              // 0..127
            const int hc = (idx & 3) << 3;         // half col 0,8,16,24
            const uint32_t da = s_base + (uint32_t)((st * ABUF_H + row * HSTR + hc) << 1);
            cp16(da, A + (size_t)(m0 + row) * K + k0 + hc);
        }
        #pragma unroll
        for (int c = 0; c < 2; c++) {
            const int idx = tid + (c << 7);        // 0..255
            const int row = idx >> 2;              // 0..63
            const int hc = (idx & 3) << 3;
            const uint32_t dw = s_base +
                (uint32_t)(((GSTAGES * ABUF_H + st * BBUF_H) + row * HSTR + hc) << 1);
            cp16(dw, W + (size_t)(n0 + row) * K + k0 + hc);
        }
        asm volatile("cp.async.commit_group;");
    };

    issue(0, 0);
    if (nt > 1) issue(1, 1);

    int buf = 0;
    for (int t = 0; t < nt; t++) {
        if (t + 1 < nt)
            asm volatile("cp.async.wait_group 1;");
        else
            asm volatile("cp.async.wait_group 0;");
        __syncthreads();

        if (t + 2 < nt) {
            int nb = buf + 2; if (nb >= GSTAGES) nb -= GSTAGES;
            issue(t + 2, nb);
        }

        const uint32_t abase = s_base + (uint32_t)((buf * ABUF_H) << 1);
        const uint32_t bbase = s_base + (uint32_t)(((GSTAGES * ABUF_H + buf * BBUF_H)) << 1);

        #pragma unroll
        for (int kk = 0; kk < 2; kk++) {           // 2 x k16 per BK=32
            uint32_t af[4][4], bf[4][2];
            #pragma unroll
            for (int mi = 0; mi < 4; mi++)
                ldsm4(af[mi][0], af[mi][1], af[mi][2], af[mi][3],
                      abase + a_off[mi] + kk * 32);
            #pragma unroll
            for (int j = 0; j < 2; j++)
                ldsm4(bf[2*j][0], bf[2*j][1], bf[2*j+1][0], bf[2*j+1][1],
                      bbase + b_off[j] + kk * 32);
            #pragma unroll
            for (int mi = 0; mi < 4; mi++)
                #pragma unroll
                for (int nj = 0; nj < 4; nj++)
                    mma_f16(acc[mi][nj], af[mi], bf[nj]);
        }
        buf = (buf + 1 == GSTAGES) ? 0 : buf + 1;
    }

    // ------------------------------ epilogue -------------------------------
    if (ksplit) {
        float* P = f0 + (size_t)blockIdx.z * M * Nper;
        #pragma unroll
        for (int mi = 0; mi < 4; mi++) {
            const int m = m0 + wm + mi * 16 + (lane >> 2);
            #pragma unroll
            for (int nj = 0; nj < 4; nj++) {
                const int n = n0 + wn + nj * 8 + ((lane & 3) << 1);
                #pragma unroll
                for (int r = 0; r < 2; r++) {
                    const int mm = m + r * 8;
                    *reinterpret_cast<float2*>(&P[(size_t)mm * Nper + n]) =
                        make_float2(acc[mi][nj][r * 2 + 0], acc[mi][nj][r * 2 + 1]);
                }
            }
        }
        return;
    }
    #pragma unroll
    for (int mi = 0; mi < 4; mi++) {
        const int m = m0 + wm + mi * 16 + (lane >> 2);
        #pragma unroll
        for (int nj = 0; nj < 4; nj++) {
            const int n = n0 + wn + nj * 8 + ((lane & 3) << 1);
            const float b0v = bias[n], b1v = bias[n + 1];
            #pragma unroll
            for (int r = 0; r < 2; r++) {
                const int mm = m + r * 8;
                float v0 = acc[mi][nj][r * 2 + 0] + b0v;
                float v1 = acc[mi][nj][r * 2 + 1] + b1v;
                if (relu) { v0 = fmaxf(v0, 0.0f); v1 = fmaxf(v1, 0.0f); }
                if (res) {
                    v0 += res[(size_t)mm * Nper + n];
                    v1 += res[(size_t)mm * Nper + n + 1];
                }
                if (out16) {
                    if (mode == 1) {
                        int h = n >> 6, hd = n & 63;
                        int b = mm >> 11, s = mm & (NS - 1);
                        *reinterpret_cast<__half2*>(
                            &H[(((size_t)(b * NH + h)) * NS + s) * NHD + hd]) =
                            __floats2half2_rn(v0, v1);
                    } else if (mode == 2) {
                        int h = n >> 6, hd = n & 63;
                        int b = mm >> 11, s = mm & (NS - 1);
                        const size_t vb = (((size_t)(b * NH + h)) * NHD + hd) * NS + s;
                        H[vb] = __float2half_rn(v0);
                        H[vb + NS] = __float2half_rn(v1);
                    } else {
                        *reinterpret_cast<__half2*>(&H[(size_t)mm * Nper + n]) =
                            __floats2half2_rn(v0, v1);
                    }
                } else {
                    *reinterpret_cast<float2*>(&f0[(size_t)mm * Nper + n]) =
                        make_float2(v0, v1);
                }
            }
        }
    }
}

// ===========================================================================
// FP16 tensor-core flash attention (R14 winner, reverted from R15).
// 64q x 64k tiles, 128 threads / 4 warps; diagonal-first; log2 softmax.
// ===========================================================================
#define ASTR 72                         // halfs per attn smem row (144 B)
#define ATILE_H (64*ASTR)               // 4608 halfs = 9216 B
#define ATT_SMEM (5*ATILE_H*2)          // 46080 bytes
#define LOG2E 1.4426950408889634f

__global__ __launch_bounds__(128, 3) void attn_tc(
    const __half* __restrict__ Q, const __half* __restrict__ K,
    const __half* __restrict__ V, __half* __restrict__ O)
{
    extern __shared__ __half smh[];

    const int tid = threadIdx.x, lane = tid & 31, warp = tid >> 5;
    const int q0 = (int)(gridDim.x - 1 - blockIdx.x) << 6;   // heavy CTAs first
    const int bh = blockIdx.y;
    const int h = bh % NH, b = bh / NH;
    const size_t base = (size_t)bh * NS * NHD;
    const float slope2 = exp2f(-(8.0f / NH) * (float)(h + 1)) * LOG2E;
    const float qk_scale = 0.125f * LOG2E;

    const uint32_t s_base = (uint32_t)__cvta_generic_to_shared(smh);
    const uint32_t qs_b = s_base;                                   // Qs / Ps
    const uint32_t kb[2] = { s_base + 1 * ATILE_H * 2, s_base + 3 * ATILE_H * 2 };
    const uint32_t vb[2] = { s_base + 2 * ATILE_H * 2, s_base + 4 * ATILE_H * 2 };
    __half* Ps = smh;

    const int a_row = (warp << 4) + (lane & 15);
    const uint32_t a_off = (uint32_t)(a_row * ASTR * 2 + ((lane >> 4) << 4));
    const int b_row = (lane & 7) + ((lane >> 4) << 3);
    const uint32_t b_colb = (uint32_t)(((lane >> 3) & 1) << 4);
    uint32_t b_off[4];
    #pragma unroll
    for (int jj = 0; jj < 4; jj++)
        b_off[jj] = (uint32_t)((b_row + 16 * jj) * ASTR * 2) + b_colb;

    auto fill = [&](int buf, int kn) {
        #pragma unroll
        for (int c = 0; c < 4; c++) {
            const int idx = tid + (c << 7);        // 0..511
            const int row = idx >> 3;              // 0..63
            const int hc = (idx & 7) << 3;         // half col 0..56
            const uint32_t soff = (uint32_t)((row * ASTR + hc) << 1);
            cp16(kb[buf] + soff, K + base + (size_t)(kn + row) * NHD + hc);
            cp16(vb[buf] + soff, V + base + (size_t)row * NS + kn + hc);
        }
        asm volatile("cp.async.commit_group;");
    };

    const int nt = (q0 >> 6) + 1;
    const int tf = nt - 1;                          // diagonal tile first

    #pragma unroll
    for (int c = 0; c < 4; c++) {
        const int idx = tid + (c << 7);
        const int row = idx >> 3;
        const int hc = (idx & 7) << 3;
        cp16(qs_b + (uint32_t)((row * ASTR + hc) << 1),
             Q + base + (size_t)(q0 + row) * NHD + hc);
    }
    fill(0, tf << 6);
    asm volatile("cp.async.wait_group 0;");
    __syncthreads();

    uint32_t qf[4][4];
    #pragma unroll
    for (int kk = 0; kk < 4; kk++)
        ldsm4(qf[kk][0], qf[kk][1], qf[kk][2], qf[kk][3], qs_b + a_off + kk * 32);

    float acc_o[8][4] = {};
    float m_r[2] = {-1e30f, -1e30f};
    float l_r[2] = {0.0f, 0.0f};
    const int qrow = q0 + (warp << 4) + (lane >> 2);

    for (int i = 0; i < nt; i++) {
        const int t = tf - i;
        const int k0 = t << 6;
        const int buf = i & 1;
        if (i > 0) {
            asm volatile("cp.async.wait_group 0;");
            __syncthreads();
        }

        if (i + 1 < nt)
            fill(buf ^ 1, (t - 1) << 6);

        // ---- S = Q K^T  (4 x k16 over d=64) ----
        float sc[8][4] = {};
        #pragma unroll
        for (int kk = 0; kk < 4; kk++) {
            uint32_t bf[8][2];
            #pragma unroll
            for (int jj = 0; jj < 4; jj++)
                ldsm4(bf[2*jj][0], bf[2*jj][1], bf[2*jj+1][0], bf[2*jj+1][1],
                      kb[buf] + b_off[jj] + kk * 32);
            #pragma unroll
            for (int j = 0; j < 8; j++)
                mma_f16(sc[j], qf[kk], bf[j]);
        }

        // ---- scale + alibi + causal + online softmax (log2 domain) ----
        #pragma unroll
        for (int r = 0; r < 2; r++) {
            const int q = qrow + r * 8;
            float mx = -1e30f;
            #pragma unroll
            for (int j = 0; j < 8; j++) {
                int kc = k0 + 8 * j + ((lane & 3) << 1);
                float s0 = fmaf(sc[j][2*r+0], qk_scale, slope2 * (float)(kc - q));
                float s1 = fmaf(sc[j][2*r+1], qk_scale, slope2 * (float)(kc + 1 - q));
                if (kc > q)     s0 = -1e30f;
                if (kc + 1 > q) s1 = -1e30f;
                sc[j][2*r+0] = s0; sc[j][2*r+1] = s1;
                mx = fmaxf(mx, fmaxf(s0, s1));
            }
            mx = fmaxf(mx, __shfl_xor_sync(0xffffffffu, mx, 1));
            mx = fmaxf(mx, __shfl_xor_sync(0xffffffffu, mx, 2));
            const float mnew = fmaxf(m_r[r], mx);
            if (__any_sync(0xffffffffu, mnew > m_r[r])) {
                const float alpha = ex2f(m_r[r] - mnew);
                l_r[r] *= alpha;
                #pragma unroll
                for (int j = 0; j < 8; j++) {
                    acc_o[j][2*r+0] *= alpha;
                    acc_o[j][2*r+1] *= alpha;
                }
                m_r[r] = mnew;
            }
            float sum = 0.0f;
            #pragma unroll
            for (int j = 0; j < 8; j++) {
                float p0 = ex2f(sc[j][2*r+0] - m_r[r]);
                float p1 = ex2f(sc[j][2*r+1] - m_r[r]);
                sc[j][2*r+0] = p0; sc[j][2*r+1] = p1;
                sum += p0 + p1;
            }
            sum += __shfl_xor_sync(0xffffffffu, sum, 1);
            sum += __shfl_xor_sync(0xffffffffu, sum, 2);
            l_r[r] += sum;
        }

        // ---- stage P as fp16 in smem (warp-private rows of Qs region) ----
        __syncwarp();
        #pragma unroll
        for (int r = 0; r < 2; r++) {
            const int rl = (warp << 4) + (lane >> 2) + r * 8;
            #pragma unroll
            for (int j = 0; j < 8; j++) {
                *reinterpret_cast<__half2*>(&Ps[rl * ASTR + 8 * j + ((lane & 3) << 1)]) =
                    __floats2half2_rn(sc[j][2*r+0], sc[j][2*r+1]);
            }
        }
        __syncwarp();

        // ---- O += P V  (4 x k16 over keys) ----
        #pragma unroll
        for (int kk = 0; kk < 4; kk++) {
            uint32_t pf[4];
            ldsm4(pf[0], pf[1], pf[2], pf[3], qs_b + a_off + kk * 32);
            uint32_t bf[8][2];
            #pragma unroll
            for (int jj = 0; jj < 4; jj++)
                ldsm4(bf[2*jj][0], bf[2*jj][1], bf[2*jj+1][0], bf[2*jj+1][1],
                      vb[buf] + b_off[jj] + kk * 32);
            #pragma unroll
            for (int j = 0; j < 8; j++)
                mma_f16(acc_o[j], pf, bf[j]);
        }
    }

    // ---- normalize and write O (fp16, (B,S,D)) ----
    #pragma unroll
    for (int r = 0; r < 2; r++) {
        const int q = qrow + r * 8;
        const float inv = 1.0f / l_r[r];
        #pragma unroll
        for (int j = 0; j < 8; j++) {
            const int d = (h << 6) + 8 * j + ((lane & 3) << 1);
            *reinterpret_cast<__half2*>(&O[((size_t)(b * NS + q)) * ND + d]) =
                __floats2half2_rn(acc_o[j][2*r+0] * inv, acc_o[j][2*r+1] * inv);
        }
    }
}

// ---------------------------------------------------------------------------
// Fused split-K reduce + bias + residual + LayerNorm (768). Single pass.
// x = p0[row] + p1[row] + bias[col] + res[row,col]; then LN; dual output.
// ---------------------------------------------------------------------------
__global__ __launch_bounds__(256) void ln2_kernel(
    const float* __restrict__ P0, const float* __restrict__ P1,
    const float* __restrict__ bias, const float* __restrict__ res,
    const float* __restrict__ g, const float* __restrict__ be,
    float* __restrict__ Y, __half* __restrict__ Y16)
{
    __shared__ float sred[18];
    const int row = blockIdx.x;
    const int tid = threadIdx.x, lane = tid & 31, warp = tid >> 5;

    float4 xv = make_float4(0.0f, 0.0f, 0.0f, 0.0f);
    if (tid < 192) {
        const size_t off = (size_t)row * ND + (tid << 2);
        float4 a = *reinterpret_cast<const float4*>(P0 + off);
        float4 c = *reinterpret_cast<const float4*>(P1 + off);
        float4 bv = *reinterpret_cast<const float4*>(bias + (tid << 2));
        float4 rv = *reinterpret_cast<const float4*>(res + off);
        xv.x = a.x + c.x + bv.x + rv.x;
        xv.y = a.y + c.y + bv.y + rv.y;
        xv.z = a.z + c.z + bv.z + rv.z;
        xv.w = a.w + c.w + bv.w + rv.w;
    }

    float s = xv.x + xv.y + xv.z + xv.w;
    float q = fmaf(xv.x, xv.x, fmaf(xv.y, xv.y, fmaf(xv.z, xv.z, xv.w * xv.w)));
    #pragma unroll
    for (int off = 16; off > 0; off >>= 1) {
        s += __shfl_xor_sync(0xffffffffu, s, off);
        q += __shfl_xor_sync(0xffffffffu, q, off);
    }
    if (lane == 0) { sred[warp] = s; sred[warp + 8] = q; }
    __syncthreads();
    if (warp == 0) {
        float s2 = (lane < 8) ? sred[lane] : 0.0f;
        float q2 = (lane < 8) ? sred[lane + 8] : 0.0f;
        #pragma unroll
        for (int off = 4; off > 0; off >>= 1) {
            s2 += __shfl_xor_sync(0xffffffffu, s2, off);
            q2 += __shfl_xor_sync(0xffffffffu, q2, off);
        }
        if (lane == 0) {
            float mu = s2 * (1.0f / ND);
            float var = q2 * (1.0f / ND) - mu * mu;
            sred[16] = mu;
            sred[17] = rsqrtf(var + 1e-5f);
        }
    }
    __syncthreads();
    const float mu = sred[16], rstd = sred[17];

    if (tid < 192) {
        float4 gv = *reinterpret_cast<const float4*>(g + (tid << 2));
        float4 bv = *reinterpret_cast<const float4*>(be + (tid << 2));
        float4 yv;
        yv.x = (xv.x - mu) * rstd * gv.x + bv.x;
        yv.y = (xv.y - mu) * rstd * gv.y + bv.y;
        yv.z = (xv.z - mu) * rstd * gv.z + bv.z;
        yv.w = (xv.w - mu) * rstd * gv.w + bv.w;
        *reinterpret_cast<float4*>(Y + (size_t)row * ND + (tid << 2)) = yv;
        if (Y16) {
            *reinterpret_cast<__half2*>(Y16 + (size_t)row * ND + (tid << 2)) =
                __floats2half2_rn(yv.x, yv.y);
            *reinterpret_cast<__half2*>(Y16 + (size_t)row * ND + (tid << 2) + 2) =
                __floats2half2_rn(yv.z, yv.w);
        }
    }
}

// ---------------------------------------------------------------------------
extern "C" void kernel_launch(void* const* d_in, const int* in_sizes, int n_in,
                              void* d_out, int out_size)
{
    const float* x   = (const float*)d_in[0];
    // d_in[1] = mask, d_in[2] = alibi_bias  (computed analytically, not read)
    const float* wq  = (const float*)d_in[3];
    const float* bq  = (const float*)d_in[4];
    const float* wk  = (const float*)d_in[5];
    const float* bk  = (const float*)d_in[6];
    const float* wv  = (const float*)d_in[7];
    const float* bv  = (const float*)d_in[8];
    const float* wo  = (const float*)d_in[9];
    const float* bo  = (const float*)d_in[10];
    const float* w1  = (const float*)d_in[11];
    const float* b1  = (const float*)d_in[12];
    const float* w2  = (const float*)d_in[13];
    const float* b2  = (const float*)d_in[14];
    const float* g1  = (const float*)d_in[15];
    const float* be1 = (const float*)d_in[16];
    const float* g2  = (const float*)d_in[17];
    const float* be2 = (const float*)d_in[18];
    float* out = (float*)d_out;

    __half *xh, *wqh, *wkh, *wvh, *woh, *w1h, *w2h;
    __half *qh, *kh, *vh, *attnh, *x1h, *ffh;
    float *part_p, *x1_p;
    cudaGetSymbolAddress((void**)&xh,   g_xh);
    cudaGetSymbolAddress((void**)&wqh,  g_wqh);
    cudaGetSymbolAddress((void**)&wkh,  g_wkh);
    cudaGetSymbolAddress((void**)&wvh,  g_wvh);
    cudaGetSymbolAddress((void**)&woh,  g_woh);
    cudaGetSymbolAddress((void**)&w1h,  g_w1h);
    cudaGetSymbolAddress((void**)&w2h,  g_w2h);
    cudaGetSymbolAddress((void**)&qh,   g_qh);
    cudaGetSymbolAddress((void**)&kh,   g_kh);
    cudaGetSymbolAddress((void**)&vh,   g_vh);
    cudaGetSymbolAddress((void**)&attnh,g_attnh);
    cudaGetSymbolAddress((void**)&x1h,  g_x1h);
    cudaGetSymbolAddress((void**)&ffh,  g_ffh);
    cudaGetSymbolAddress((void**)&part_p,g_part);
    cudaGetSymbolAddress((void**)&x1_p, g_x1);

    cudaFuncSetAttribute(attn_tc, cudaFuncAttributeMaxDynamicSharedMemorySize, ATT_SMEM);
    cudaFuncSetAttribute(gemm_h, cudaFuncAttributeMaxDynamicSharedMemorySize, GEMM_SMEM);

    // ONE fused fp32->fp16 conversion launch (x + all 6 weights)
    cvt7<<<CVT_TOTAL/1024, 256>>>(x, xh, wq, wqh, wk, wkh, wv, wvh,
                                  wo, woh, w1, w1h, w2, w2h);

    // Fused QKV (1152 CTAs): Q,K -> (B,H,S,HD) fp16; V -> (B,H,HD,S) fp16
    gemm_h<<<dim3(3*ND/64, NM/128), 128, GEMM_SMEM>>>(
        xh, wqh, wkh, wvh, bq, bk, bv, nullptr,
        qh, kh, vh, nullptr,
        NM, ND, ND, 0, 1, 1, 1, 2, 0);

    // attention -> fp16 (B,S,D)
    attn_tc<<<dim3(NS/64, NB*NH), 128, ATT_SMEM>>>(qh, kh, vh, attnh);

    // O projection: split-K=2 (768 CTAs), raw partials; LN1 fuses the reduce
    gemm_h<<<dim3(ND/64, NM/128, 2), 128, GEMM_SMEM>>>(
        attnh, woh, woh, woh, bo, bo, bo, nullptr,
        nullptr, nullptr, nullptr, part_p,
        NM, ND, ND, 0, 0, 0, 0, 0, 1);
    ln2_kernel<<<NM, 256>>>(part_p, part_p + (size_t)NM*ND, bo, x,
                            g1, be1, x1_p, x1h);

    // FFN1 (relu, fp16 out; 1536 CTAs, non-split)
    gemm_h<<<dim3(NFF/64, NM/128), 128, GEMM_SMEM>>>(
        x1h, w1h, w1h, w1h, b1, b1, b1, nullptr,
        ffh, ffh, ffh, nullptr,
        NM, NFF, ND, 1, 1, 0, 0, 0, 0);

    // FFN2: split-K=2 (768 CTAs), raw partials; LN2 fuses reduce + residual
    gemm_h<<<dim3(ND/64, NM/128, 2), 128, GEMM_SMEM>>>(
        ffh, w2h, w2h, w2h, b2, b2, b2, nullptr,
        nullptr, nullptr, nullptr, part_p,
        NM, ND, NFF, 0, 0, 0, 0, 0, 1);
    ln2_kernel<<<NM, 256>>>(part_p, part_p + (size_t)NM*ND, b2, x1_p,
                            g2, be2, out, nullptr);
}